// round 7
// baseline (speedup 1.0000x reference)
#include <cuda_runtime.h>
#include <cstdint>

// FreezedScaledFakeQuantize: out = (clip(round(x/s + zp), qmin, qmax) - zp) * s
// X: [8192, 8192] fp32; scale/zp: [8192, 64] fp32 (group size 128); qmin/qmax: int32 scalars.
//
// HBM-bound streaming elementwise op (~538 MiB traffic -> ~80-100us roofline).
// Design:
//   - 2x independent float4 (128-bit) loads per thread, FRONT-BATCHED for MLP=2
//     (halves exposed DRAM latency; MLP_p1=2 stays in the low cross-CTA-spread regime)
//   - block owns 512 contiguous vecs; thread t -> vec t and vec t+256 (coalesced;
//     each warp-access spans exactly one 128-elem group -> warp-uniform scale/zp)
//   - streaming hints: __ldcs on X, __stcs on out (512 MiB stream; keep the
//     2 MiB scale/zp tables L2-resident via __ldg)
//   - EXACT __fdiv_rn + rintf (round-half-even): bit-exact vs the JAX reference.
//     Pipe audit at full HBM rate (3.5 elem/cyc/SM): issue 1.3/4, MUFU 0.11/0.5,
//     fma 0.9/2 -> exact divide is free on a memory-bound kernel.
//   - Pure 32-bit index math (2^24 vecs, 256 MiB max offset): no IMAD.WIDE chains.

static constexpr int ROWS = 8192;
static constexpr int COLS = 8192;
static constexpr int GROUP_SIZE = 128;
static constexpr int N_GROUPS = COLS / GROUP_SIZE;         // 64
static constexpr int VECS_PER_ROW = COLS / 4;              // 2048
static constexpr unsigned TOTAL_VECS = (unsigned)ROWS * VECS_PER_ROW;  // 16,777,216 = 2^24

static constexpr int THREADS = 256;
static constexpr int VECS_PER_THREAD = 2;
static constexpr int VECS_PER_BLOCK = THREADS * VECS_PER_THREAD;  // 512

__device__ __forceinline__ float4 fq4_exact(float4 x, float s, float zp,
                                            float qmin, float qmax)
{
    // Exactly mirrors: clip(round(x/s + zp), qmin, qmax); (q - zp) * s
    float q0 = rintf(__fdiv_rn(x.x, s) + zp);
    float q1 = rintf(__fdiv_rn(x.y, s) + zp);
    float q2 = rintf(__fdiv_rn(x.z, s) + zp);
    float q3 = rintf(__fdiv_rn(x.w, s) + zp);
    q0 = fminf(fmaxf(q0, qmin), qmax);
    q1 = fminf(fmaxf(q1, qmin), qmax);
    q2 = fminf(fmaxf(q2, qmin), qmax);
    q3 = fminf(fmaxf(q3, qmin), qmax);
    float4 r;
    r.x = (q0 - zp) * s;
    r.y = (q1 - zp) * s;
    r.z = (q2 - zp) * s;
    r.w = (q3 - zp) * s;
    return r;
}

__global__ __launch_bounds__(THREADS)
void fake_quantize_kernel(const float* __restrict__ X,
                          const float* __restrict__ scale,
                          const float* __restrict__ zero_point,
                          const int* __restrict__ qmin_p,
                          const int* __restrict__ qmax_p,
                          float* __restrict__ out)
{
    const unsigned vid0 = blockIdx.x * VECS_PER_BLOCK + threadIdx.x;  // [b*512, b*512+256)
    const unsigned vid1 = vid0 + THREADS;                             // [b*512+256, b*512+512)

    // Front-batched independent 128-bit streaming loads -> MLP=2 per thread
    const float4 x0 = __ldcs(((const float4*)X) + vid0);
    const float4 x1 = __ldcs(((const float4*)X) + vid1);

    const float qmin = (float)__ldg(qmin_p);
    const float qmax = (float)__ldg(qmax_p);

    // Power-of-2 index math -> shifts/masks; warp-uniform per access
    const unsigned row0 = vid0 >> 11;                       // vid / 2048
    const unsigned grp0 = (vid0 & (VECS_PER_ROW - 1)) >> 5; // (vid % 2048) / 32
    const unsigned row1 = vid1 >> 11;
    const unsigned grp1 = (vid1 & (VECS_PER_ROW - 1)) >> 5;

    const float s0  = __ldg(&scale[row0 * N_GROUPS + grp0]);
    const float zp0 = __ldg(&zero_point[row0 * N_GROUPS + grp0]);
    const float s1  = __ldg(&scale[row1 * N_GROUPS + grp1]);
    const float zp1 = __ldg(&zero_point[row1 * N_GROUPS + grp1]);

    const float4 r0 = fq4_exact(x0, s0, zp0, qmin, qmax);
    const float4 r1 = fq4_exact(x1, s1, zp1, qmin, qmax);

    __stcs(((float4*)out) + vid0, r0);
    __stcs(((float4*)out) + vid1, r1);
}

extern "C" void kernel_launch(void* const* d_in, const int* in_sizes, int n_in,
                              void* d_out, int out_size)
{
    const float* X          = (const float*)d_in[0];
    const float* scale      = (const float*)d_in[1];
    const float* zero_point = (const float*)d_in[2];
    const int*   qmin       = (const int*)d_in[3];
    const int*   qmax       = (const int*)d_in[4];
    float*       out        = (float*)d_out;

    const unsigned blocks = TOTAL_VECS / VECS_PER_BLOCK;  // 32768, exact division
    fake_quantize_kernel<<<blocks, THREADS>>>(X, scale, zero_point, qmin, qmax, out);
}